// round 2
// baseline (speedup 1.0000x reference)
#include <cuda_runtime.h>
#include <math_constants.h>

// ---------------- device scratch (static __device__, sanctioned) ----------
#define NPIX_MAX (32 * 128 * 2048)   // 8,388,608 pixels

__device__ float        g_gray[NPIX_MAX];
__device__ unsigned int g_min_bits;
__device__ unsigned int g_max_bits;
__device__ unsigned int g_hist[256];
__device__ float        g_thresh;

// monotonic float<->uint encoding
__device__ __forceinline__ unsigned int f_enc(float f) {
    unsigned int u = __float_as_uint(f);
    return (u & 0x80000000u) ? ~u : (u | 0x80000000u);
}
__device__ __forceinline__ float f_dec(unsigned int e) {
    unsigned int u = (e & 0x80000000u) ? (e & 0x7FFFFFFFu) : ~e;
    return __uint_as_float(u);
}

__device__ __forceinline__ float gray_of(float r, float g, float b) {
    return fmaf(0.1140f, b, fmaf(0.5870f, g, __fmul_rn(0.2989f, r)));
}

// ---------------- K0: reset state (inside graph, every replay) -------------
__global__ void init_kernel() {
    int t = threadIdx.x;
    if (t < 256) g_hist[t] = 0u;
    if (t == 0) {
        g_min_bits = 0xFFFFFFFFu;
        g_max_bits = 0x00000000u;
        g_thresh   = 0.0f;
    }
}

// ---------------- K1: gray + global min/max --------------------------------
__global__ void gray_minmax_kernel(const float* __restrict__ in, int npix) {
    const int ngroups = npix >> 2;
    const int tail0   = ngroups << 2;
    const float4* __restrict__ in4 = (const float4*)in;
    float4* __restrict__ gr4 = (float4*)g_gray;

    float lmin = CUDART_INF_F, lmax = -CUDART_INF_F;
    const int stride = gridDim.x * blockDim.x;

    for (int g = blockIdx.x * blockDim.x + threadIdx.x; g < ngroups; g += stride) {
        float4 a = in4[3 * g + 0];
        float4 b = in4[3 * g + 1];
        float4 c = in4[3 * g + 2];
        float g0 = gray_of(a.x, a.y, a.z);
        float g1 = gray_of(a.w, b.x, b.y);
        float g2 = gray_of(b.z, b.w, c.x);
        float g3 = gray_of(c.y, c.z, c.w);
        gr4[g] = make_float4(g0, g1, g2, g3);
        lmin = fminf(lmin, fminf(fminf(g0, g1), fminf(g2, g3)));
        lmax = fmaxf(lmax, fmaxf(fmaxf(g0, g1), fmaxf(g2, g3)));
    }
    // distributed scalar tail (usually empty)
    for (int p = tail0 + blockIdx.x * blockDim.x + threadIdx.x; p < npix; p += stride) {
        float gg = gray_of(in[3 * p], in[3 * p + 1], in[3 * p + 2]);
        g_gray[p] = gg;
        lmin = fminf(lmin, gg);
        lmax = fmaxf(lmax, gg);
    }

    for (int o = 16; o; o >>= 1) {
        lmin = fminf(lmin, __shfl_xor_sync(0xFFFFFFFFu, lmin, o));
        lmax = fmaxf(lmax, __shfl_xor_sync(0xFFFFFFFFu, lmax, o));
    }
    __shared__ float smin[8], smax[8];
    int wid = threadIdx.x >> 5, lid = threadIdx.x & 31;
    if (lid == 0) { smin[wid] = lmin; smax[wid] = lmax; }
    __syncthreads();
    if (threadIdx.x == 0) {
        float bmin = smin[0], bmax = smax[0];
        int nw = (blockDim.x + 31) >> 5;
        for (int i = 1; i < nw; i++) {
            bmin = fminf(bmin, smin[i]);
            bmax = fmaxf(bmax, smax[i]);
        }
        atomicMin(&g_min_bits, f_enc(bmin));
        atomicMax(&g_max_bits, f_enc(bmax));
    }
}

// ---------------- K2: 256-bin histogram over [vmin, vmax] ------------------
__global__ void hist_kernel(int npix) {
    __shared__ unsigned int sh[256 * 8];
    for (int i = threadIdx.x; i < 256 * 8; i += blockDim.x) sh[i] = 0u;
    __syncthreads();

    const float vmin = f_dec(g_min_bits);
    const float vmax = f_dec(g_max_bits);
    const float scale = 256.0f / (vmax - vmin);

    unsigned int* my = sh + ((threadIdx.x >> 5) & 7) * 256;
    const int ngroups = npix >> 2;
    const int tail0   = ngroups << 2;
    const int stride  = gridDim.x * blockDim.x;
    const float4* __restrict__ gr4 = (const float4*)g_gray;

    for (int g = blockIdx.x * blockDim.x + threadIdx.x; g < ngroups; g += stride) {
        float4 v = gr4[g];
        int b0 = min(255, max(0, (int)((v.x - vmin) * scale)));
        int b1 = min(255, max(0, (int)((v.y - vmin) * scale)));
        int b2 = min(255, max(0, (int)((v.z - vmin) * scale)));
        int b3 = min(255, max(0, (int)((v.w - vmin) * scale)));
        atomicAdd(&my[b0], 1u);
        atomicAdd(&my[b1], 1u);
        atomicAdd(&my[b2], 1u);
        atomicAdd(&my[b3], 1u);
    }
    for (int p = tail0 + blockIdx.x * blockDim.x + threadIdx.x; p < npix; p += stride) {
        int b = min(255, max(0, (int)((g_gray[p] - vmin) * scale)));
        atomicAdd(&my[b], 1u);
    }
    __syncthreads();
    for (int i = threadIdx.x; i < 256; i += blockDim.x) {
        unsigned int s = 0;
        #pragma unroll
        for (int r = 0; r < 8; r++) s += sh[r * 256 + i];
        if (s) atomicAdd(&g_hist[i], s);
    }
}

// ---------------- K3: Otsu argmax (ALL scratch in shared — no local mem) ---
__global__ void otsu_kernel() {
    __shared__ float centers[256];
    __shared__ float w1[256], s1[256], w2[256], s2[256];

    const float vmin = f_dec(g_min_bits);
    const float vmax = f_dec(g_max_bits);
    const float step = __fmul_rn(__fadd_rn(vmax, -vmin), 1.0f / 256.0f);

    int t = threadIdx.x;   // 256 threads
    {
        float e0 = __fadd_rn(vmin, __fmul_rn(step, (float)t));
        float e1 = (t == 255) ? vmax : __fadd_rn(vmin, __fmul_rn(step, (float)(t + 1)));
        centers[t] = __fmul_rn(__fadd_rn(e0, e1), 0.5f);
    }
    __syncthreads();

    if (t == 0) {
        float cw = 0.0f, cs = 0.0f;
        for (int i = 0; i < 256; i++) {
            float h = (float)g_hist[i];
            cw = __fadd_rn(cw, h);
            cs = __fadd_rn(cs, __fmul_rn(h, centers[i]));
            w1[i] = cw; s1[i] = cs;
        }
        cw = 0.0f; cs = 0.0f;
        for (int i = 255; i >= 0; i--) {
            float h = (float)g_hist[i];
            cw = __fadd_rn(cw, h);
            cs = __fadd_rn(cs, __fmul_rn(h, centers[i]));
            w2[i] = cw; s2[i] = cs;
        }
        float best = -CUDART_INF_F;
        int bidx = 0;
        for (int k = 0; k < 255; k++) {
            float m1 = s1[k] / fmaxf(w1[k], 1.0f);
            float m2 = s2[k + 1] / fmaxf(w2[k + 1], 1.0f);
            float d = __fadd_rn(m1, -m2);
            float v = __fmul_rn(__fmul_rn(w1[k], w2[k + 1]), __fmul_rn(d, d));
            if (v > best) { best = v; bidx = k; }   // first-argmax (jnp semantics)
        }
        g_thresh = centers[bidx];
    }
}

// ---------------- K4: binarize + tile to 3 channels ------------------------
__global__ void binarize_kernel(float* __restrict__ out, int npix) {
    const float t = g_thresh;
    const int ngroups = npix >> 2;
    const int tail0   = ngroups << 2;
    const int stride  = gridDim.x * blockDim.x;
    const float4* __restrict__ gr4 = (const float4*)g_gray;
    float4* __restrict__ o4 = (float4*)out;

    for (int g = blockIdx.x * blockDim.x + threadIdx.x; g < ngroups; g += stride) {
        float4 v = gr4[g];
        float b0 = (v.x > t) ? 1.0f : 0.0f;
        float b1 = (v.y > t) ? 1.0f : 0.0f;
        float b2 = (v.z > t) ? 1.0f : 0.0f;
        float b3 = (v.w > t) ? 1.0f : 0.0f;
        o4[3 * g + 0] = make_float4(b0, b0, b0, b1);
        o4[3 * g + 1] = make_float4(b1, b1, b2, b2);
        o4[3 * g + 2] = make_float4(b2, b3, b3, b3);
    }
    for (int p = tail0 + blockIdx.x * blockDim.x + threadIdx.x; p < npix; p += stride) {
        float b = (g_gray[p] > t) ? 1.0f : 0.0f;
        out[3 * p + 0] = b;
        out[3 * p + 1] = b;
        out[3 * p + 2] = b;
    }
}

// ---------------- launch ---------------------------------------------------
extern "C" void kernel_launch(void* const* d_in, const int* in_sizes, int n_in,
                              void* d_out, int out_size) {
    const float* in = (const float*)d_in[0];
    float* out = (float*)d_out;
    int npix = in_sizes[0] / 3;

    const int THREADS = 256;
    const int GRID = 148 * 8;

    init_kernel<<<1, 256>>>();
    gray_minmax_kernel<<<GRID, THREADS>>>(in, npix);
    hist_kernel<<<GRID, THREADS>>>(npix);
    otsu_kernel<<<1, 256>>>();
    binarize_kernel<<<GRID, THREADS>>>(out, npix);
}

// round 3
// speedup vs baseline: 1.4779x; 1.4779x over previous
#include <cuda_runtime.h>
#include <math_constants.h>

#define NPIX_MAX (32 * 128 * 2048)
#define TB 256

__device__ float        g_gray[NPIX_MAX];
__device__ unsigned int g_min_bits;
__device__ unsigned int g_max_bits;
__device__ unsigned int g_hist[256];
__device__ float        g_thresh;

__device__ __forceinline__ unsigned int f_enc(float f) {
    unsigned int u = __float_as_uint(f);
    return (u & 0x80000000u) ? ~u : (u | 0x80000000u);
}
__device__ __forceinline__ float f_dec(unsigned int e) {
    unsigned int u = (e & 0x80000000u) ? (e & 0x7FFFFFFFu) : ~e;
    return __uint_as_float(u);
}
__device__ __forceinline__ float gray_of(float r, float g, float b) {
    return fmaf(0.1140f, b, fmaf(0.5870f, g, __fmul_rn(0.2989f, r)));
}

// ---------------- K0: reset state ------------------------------------------
__global__ void init_kernel() {
    int t = threadIdx.x;
    if (t < 256) g_hist[t] = 0u;
    if (t == 0) {
        g_min_bits = 0xFFFFFFFFu;
        g_max_bits = 0x00000000u;
        g_thresh   = 0.0f;
    }
}

// ---------------- K1: gray + min/max (smem-staged coalesced loads) ---------
__global__ void gray_minmax_kernel(const float* __restrict__ in, int npix) {
    __shared__ float4 stage[TB * 3];            // 12 KB
    const int ngroups = npix >> 2;              // float4 gray groups
    const int nf4     = ngroups * 3;            // input float4 count (vector part)
    const int ntiles  = (ngroups + TB - 1) / TB;
    const float4* __restrict__ in4 = (const float4*)in;
    float4* __restrict__ gr4 = (float4*)g_gray;
    const int t = threadIdx.x;

    float lmin = CUDART_INF_F, lmax = -CUDART_INF_F;

    for (int tile = blockIdx.x; tile < ntiles; tile += gridDim.x) {
        const int gbase = tile * TB;
        const int fbase = gbase * 3;
        #pragma unroll
        for (int j = 0; j < 3; j++) {
            int idx = t + j * TB;
            if (fbase + idx < nf4) stage[idx] = in4[fbase + idx];
        }
        __syncthreads();
        const int g = gbase + t;
        if (g < ngroups) {
            float4 a = stage[3 * t + 0];
            float4 b = stage[3 * t + 1];
            float4 c = stage[3 * t + 2];
            float g0 = gray_of(a.x, a.y, a.z);
            float g1 = gray_of(a.w, b.x, b.y);
            float g2 = gray_of(b.z, b.w, c.x);
            float g3 = gray_of(c.y, c.z, c.w);
            gr4[g] = make_float4(g0, g1, g2, g3);
            lmin = fminf(lmin, fminf(fminf(g0, g1), fminf(g2, g3)));
            lmax = fmaxf(lmax, fmaxf(fmaxf(g0, g1), fmaxf(g2, g3)));
        }
        __syncthreads();
    }
    // distributed scalar tail (empty for this shape)
    const int stride = gridDim.x * blockDim.x;
    for (int p = (ngroups << 2) + blockIdx.x * blockDim.x + t; p < npix; p += stride) {
        float gg = gray_of(in[3 * p], in[3 * p + 1], in[3 * p + 2]);
        g_gray[p] = gg;
        lmin = fminf(lmin, gg);
        lmax = fmaxf(lmax, gg);
    }

    for (int o = 16; o; o >>= 1) {
        lmin = fminf(lmin, __shfl_xor_sync(0xFFFFFFFFu, lmin, o));
        lmax = fmaxf(lmax, __shfl_xor_sync(0xFFFFFFFFu, lmax, o));
    }
    __shared__ float smin[8], smax[8];
    int wid = t >> 5, lid = t & 31;
    if (lid == 0) { smin[wid] = lmin; smax[wid] = lmax; }
    __syncthreads();
    if (t == 0) {
        float bmin = smin[0], bmax = smax[0];
        for (int i = 1; i < (TB >> 5); i++) {
            bmin = fminf(bmin, smin[i]);
            bmax = fmaxf(bmax, smax[i]);
        }
        atomicMin(&g_min_bits, f_enc(bmin));
        atomicMax(&g_max_bits, f_enc(bmax));
    }
}

// ---------------- K2: 256-bin histogram ------------------------------------
__global__ void hist_kernel(int npix) {
    __shared__ unsigned int sh[256 * 8];
    for (int i = threadIdx.x; i < 256 * 8; i += blockDim.x) sh[i] = 0u;
    __syncthreads();

    const float vmin = f_dec(g_min_bits);
    const float vmax = f_dec(g_max_bits);
    const float scale = 256.0f / (vmax - vmin);

    unsigned int* my = sh + ((threadIdx.x >> 5) & 7) * 256;
    const int ngroups = npix >> 2;
    const int stride  = gridDim.x * blockDim.x;
    const float4* __restrict__ gr4 = (const float4*)g_gray;

    for (int g = blockIdx.x * blockDim.x + threadIdx.x; g < ngroups; g += stride) {
        float4 v = gr4[g];
        int b0 = min(255, max(0, (int)((v.x - vmin) * scale)));
        int b1 = min(255, max(0, (int)((v.y - vmin) * scale)));
        int b2 = min(255, max(0, (int)((v.z - vmin) * scale)));
        int b3 = min(255, max(0, (int)((v.w - vmin) * scale)));
        atomicAdd(&my[b0], 1u);
        atomicAdd(&my[b1], 1u);
        atomicAdd(&my[b2], 1u);
        atomicAdd(&my[b3], 1u);
    }
    for (int p = (ngroups << 2) + blockIdx.x * blockDim.x + threadIdx.x; p < npix; p += stride) {
        int b = min(255, max(0, (int)((g_gray[p] - vmin) * scale)));
        atomicAdd(&my[b], 1u);
    }
    __syncthreads();
    for (int i = threadIdx.x; i < 256; i += blockDim.x) {
        unsigned int s = 0;
        #pragma unroll
        for (int r = 0; r < 8; r++) s += sh[r * 256 + i];
        if (s) atomicAdd(&g_hist[i], s);
    }
}

// ---------------- K3: Otsu — shared-staged, parallel variance+argmax -------
__global__ void otsu_kernel() {
    __shared__ float h[256], c[256];
    __shared__ float w1[256], s1[256], w2[256], s2[256];
    __shared__ float bv[256];
    __shared__ int   bi[256];

    const float vmin = f_dec(g_min_bits);
    const float vmax = f_dec(g_max_bits);
    const float step = __fmul_rn(__fadd_rn(vmax, -vmin), 1.0f / 256.0f);

    const int t = threadIdx.x;
    {
        h[t] = (float)g_hist[t];
        float e0 = __fadd_rn(vmin, __fmul_rn(step, (float)t));
        float e1 = (t == 255) ? vmax : __fadd_rn(vmin, __fmul_rn(step, (float)(t + 1)));
        c[t] = __fmul_rn(__fadd_rn(e0, e1), 0.5f);
    }
    __syncthreads();

    // exact serial cumsums (matches jnp left-fold rounding) — over SHARED
    if (t == 0) {
        float cw = 0.0f, cs = 0.0f;
        for (int i = 0; i < 256; i++) {
            cw = __fadd_rn(cw, h[i]);
            cs = __fadd_rn(cs, __fmul_rn(h[i], c[i]));
            w1[i] = cw; s1[i] = cs;
        }
        cw = 0.0f; cs = 0.0f;
        for (int i = 255; i >= 0; i--) {
            cw = __fadd_rn(cw, h[i]);
            cs = __fadd_rn(cs, __fmul_rn(h[i], c[i]));
            w2[i] = cw; s2[i] = cs;
        }
    }
    __syncthreads();

    // parallel per-split variance (divisions run concurrently)
    float v = -CUDART_INF_F;
    if (t < 255) {
        float m1 = s1[t] / fmaxf(w1[t], 1.0f);
        float m2 = s2[t + 1] / fmaxf(w2[t + 1], 1.0f);
        float d = __fadd_rn(m1, -m2);
        v = __fmul_rn(__fmul_rn(w1[t], w2[t + 1]), __fmul_rn(d, d));
    }
    bv[t] = v; bi[t] = t;
    __syncthreads();
    // strict-> reduce keeps LOWEST index on ties == jnp first-argmax
    for (int s = 128; s; s >>= 1) {
        if (t < s) {
            if (bv[t + s] > bv[t]) { bv[t] = bv[t + s]; bi[t] = bi[t + s]; }
        }
        __syncthreads();
    }
    if (t == 0) g_thresh = c[bi[0]];
}

// ---------------- K4: binarize + tile (smem-staged coalesced stores) -------
__global__ void binarize_kernel(float* __restrict__ out, int npix) {
    __shared__ float4 stage[TB * 3];            // 12 KB
    const float thr = g_thresh;
    const int ngroups = npix >> 2;
    const int nf4     = ngroups * 3;
    const int ntiles  = (ngroups + TB - 1) / TB;
    const float4* __restrict__ gr4 = (const float4*)g_gray;
    float4* __restrict__ o4 = (float4*)out;
    const int t = threadIdx.x;

    for (int tile = blockIdx.x; tile < ntiles; tile += gridDim.x) {
        const int gbase = tile * TB;
        const int g = gbase + t;
        if (g < ngroups) {
            float4 v = gr4[g];
            float b0 = (v.x > thr) ? 1.0f : 0.0f;
            float b1 = (v.y > thr) ? 1.0f : 0.0f;
            float b2 = (v.z > thr) ? 1.0f : 0.0f;
            float b3 = (v.w > thr) ? 1.0f : 0.0f;
            stage[3 * t + 0] = make_float4(b0, b0, b0, b1);
            stage[3 * t + 1] = make_float4(b1, b1, b2, b2);
            stage[3 * t + 2] = make_float4(b2, b3, b3, b3);
        }
        __syncthreads();
        const int fbase = gbase * 3;
        #pragma unroll
        for (int j = 0; j < 3; j++) {
            int idx = t + j * TB;
            if (fbase + idx < nf4) o4[fbase + idx] = stage[idx];
        }
        __syncthreads();
    }
    const int stride = gridDim.x * blockDim.x;
    for (int p = (ngroups << 2) + blockIdx.x * blockDim.x + t; p < npix; p += stride) {
        float b = (g_gray[p] > thr) ? 1.0f : 0.0f;
        out[3 * p + 0] = b;
        out[3 * p + 1] = b;
        out[3 * p + 2] = b;
    }
}

// ---------------- launch ---------------------------------------------------
extern "C" void kernel_launch(void* const* d_in, const int* in_sizes, int n_in,
                              void* d_out, int out_size) {
    const float* in = (const float*)d_in[0];
    float* out = (float*)d_out;
    int npix = in_sizes[0] / 3;

    const int GRID = 148 * 8;

    init_kernel<<<1, 256>>>();
    gray_minmax_kernel<<<GRID, TB>>>(in, npix);
    hist_kernel<<<GRID, TB>>>(npix);
    otsu_kernel<<<1, 256>>>();
    binarize_kernel<<<GRID, TB>>>(out, npix);
}

// round 4
// speedup vs baseline: 1.7268x; 1.1684x over previous
#include <cuda_runtime.h>
#include <math_constants.h>

#define NPIX_MAX (32 * 128 * 2048)
#define TB 256

__device__ float        g_gray[NPIX_MAX];
__device__ unsigned int g_min_bits;
__device__ unsigned int g_max_bits;
__device__ unsigned int g_hist[256];
__device__ float        g_thresh;

__device__ __forceinline__ unsigned int f_enc(float f) {
    unsigned int u = __float_as_uint(f);
    return (u & 0x80000000u) ? ~u : (u | 0x80000000u);
}
__device__ __forceinline__ float f_dec(unsigned int e) {
    unsigned int u = (e & 0x80000000u) ? (e & 0x7FFFFFFFu) : ~e;
    return __uint_as_float(u);
}
__device__ __forceinline__ float gray_of(float r, float g, float b) {
    return fmaf(0.1140f, b, fmaf(0.5870f, g, __fmul_rn(0.2989f, r)));
}

// ---------------- K0: reset state ------------------------------------------
__global__ void init_kernel() {
    int t = threadIdx.x;
    if (t < 256) g_hist[t] = 0u;
    if (t == 0) {
        g_min_bits = 0xFFFFFFFFu;
        g_max_bits = 0x00000000u;
        g_thresh   = 0.0f;
    }
}

// ---------------- K1: gray + min/max (smem-staged coalesced loads) ---------
__global__ void gray_minmax_kernel(const float* __restrict__ in, int npix) {
    __shared__ float4 stage[TB * 3];            // 12 KB
    const int ngroups = npix >> 2;
    const int nf4     = ngroups * 3;
    const int ntiles  = (ngroups + TB - 1) / TB;
    const float4* __restrict__ in4 = (const float4*)in;
    float4* __restrict__ gr4 = (float4*)g_gray;
    const int t = threadIdx.x;

    float lmin = CUDART_INF_F, lmax = -CUDART_INF_F;

    for (int tile = blockIdx.x; tile < ntiles; tile += gridDim.x) {
        const int gbase = tile * TB;
        const int fbase = gbase * 3;
        #pragma unroll
        for (int j = 0; j < 3; j++) {
            int idx = t + j * TB;
            if (fbase + idx < nf4) stage[idx] = in4[fbase + idx];
        }
        __syncthreads();
        const int g = gbase + t;
        if (g < ngroups) {
            float4 a = stage[3 * t + 0];
            float4 b = stage[3 * t + 1];
            float4 c = stage[3 * t + 2];
            float g0 = gray_of(a.x, a.y, a.z);
            float g1 = gray_of(a.w, b.x, b.y);
            float g2 = gray_of(b.z, b.w, c.x);
            float g3 = gray_of(c.y, c.z, c.w);
            gr4[g] = make_float4(g0, g1, g2, g3);
            lmin = fminf(lmin, fminf(fminf(g0, g1), fminf(g2, g3)));
            lmax = fmaxf(lmax, fmaxf(fmaxf(g0, g1), fmaxf(g2, g3)));
        }
        __syncthreads();
    }
    const int stride = gridDim.x * blockDim.x;
    for (int p = (ngroups << 2) + blockIdx.x * blockDim.x + t; p < npix; p += stride) {
        float gg = gray_of(in[3 * p], in[3 * p + 1], in[3 * p + 2]);
        g_gray[p] = gg;
        lmin = fminf(lmin, gg);
        lmax = fmaxf(lmax, gg);
    }

    for (int o = 16; o; o >>= 1) {
        lmin = fminf(lmin, __shfl_xor_sync(0xFFFFFFFFu, lmin, o));
        lmax = fmaxf(lmax, __shfl_xor_sync(0xFFFFFFFFu, lmax, o));
    }
    __shared__ float smin[8], smax[8];
    int wid = t >> 5, lid = t & 31;
    if (lid == 0) { smin[wid] = lmin; smax[wid] = lmax; }
    __syncthreads();
    if (t == 0) {
        float bmin = smin[0], bmax = smax[0];
        for (int i = 1; i < (TB >> 5); i++) {
            bmin = fminf(bmin, smin[i]);
            bmax = fmaxf(bmax, smax[i]);
        }
        atomicMin(&g_min_bits, f_enc(bmin));
        atomicMax(&g_max_bits, f_enc(bmax));
    }
}

// ---------------- K2: 256-bin histogram ------------------------------------
__global__ void hist_kernel(int npix) {
    __shared__ unsigned int sh[256 * 8];
    for (int i = threadIdx.x; i < 256 * 8; i += blockDim.x) sh[i] = 0u;
    __syncthreads();

    const float vmin = f_dec(g_min_bits);
    const float vmax = f_dec(g_max_bits);
    const float scale = 256.0f / (vmax - vmin);

    unsigned int* my = sh + ((threadIdx.x >> 5) & 7) * 256;
    const int ngroups = npix >> 2;
    const int stride  = gridDim.x * blockDim.x;
    const float4* __restrict__ gr4 = (const float4*)g_gray;

    for (int g = blockIdx.x * blockDim.x + threadIdx.x; g < ngroups; g += stride) {
        float4 v = gr4[g];
        int b0 = min(255, max(0, (int)((v.x - vmin) * scale)));
        int b1 = min(255, max(0, (int)((v.y - vmin) * scale)));
        int b2 = min(255, max(0, (int)((v.z - vmin) * scale)));
        int b3 = min(255, max(0, (int)((v.w - vmin) * scale)));
        atomicAdd(&my[b0], 1u);
        atomicAdd(&my[b1], 1u);
        atomicAdd(&my[b2], 1u);
        atomicAdd(&my[b3], 1u);
    }
    for (int p = (ngroups << 2) + blockIdx.x * blockDim.x + threadIdx.x; p < npix; p += stride) {
        int b = min(255, max(0, (int)((g_gray[p] - vmin) * scale)));
        atomicAdd(&my[b], 1u);
    }
    __syncthreads();
    for (int i = threadIdx.x; i < 256; i += blockDim.x) {
        unsigned int s = 0;
        #pragma unroll
        for (int r = 0; r < 8; r++) s += sh[r * 256 + i];
        if (s) atomicAdd(&g_hist[i], s);
    }
}

// ---------------- K3: Otsu — fully parallel Kogge-Stone scans --------------
__global__ void otsu_kernel() {
    __shared__ float c[256];
    __shared__ float w1[256], s1[256], w2[256], s2[256];
    __shared__ float bv[256];
    __shared__ int   bi[256];

    const int t = threadIdx.x;
    const float vmin = f_dec(g_min_bits);
    const float vmax = f_dec(g_max_bits);
    const float step = __fmul_rn(__fadd_rn(vmax, -vmin), 1.0f / 256.0f);

    float e0 = __fadd_rn(vmin, __fmul_rn(step, (float)t));
    float e1 = (t == 255) ? vmax : __fadd_rn(vmin, __fmul_rn(step, (float)(t + 1)));
    float ct = __fmul_rn(__fadd_rn(e0, e1), 0.5f);
    c[t] = ct;

    float hv = (float)g_hist[t];
    float hc = __fmul_rn(hv, ct);
    w1[t] = hv; s1[t] = hc;   // forward inclusive scans
    w2[t] = hv; s2[t] = hc;   // suffix (reverse) inclusive scans
    __syncthreads();

    #pragma unroll
    for (int s = 1; s < 256; s <<= 1) {
        float aw1 = (t >= s)      ? w1[t - s] : 0.0f;
        float as1 = (t >= s)      ? s1[t - s] : 0.0f;
        float aw2 = (t + s < 256) ? w2[t + s] : 0.0f;
        float as2 = (t + s < 256) ? s2[t + s] : 0.0f;
        __syncthreads();
        w1[t] = __fadd_rn(w1[t], aw1);
        s1[t] = __fadd_rn(s1[t], as1);
        w2[t] = __fadd_rn(w2[t], aw2);
        s2[t] = __fadd_rn(s2[t], as2);
        __syncthreads();
    }

    float v = -CUDART_INF_F;
    if (t < 255) {
        float m1 = s1[t] / fmaxf(w1[t], 1.0f);
        float m2 = s2[t + 1] / fmaxf(w2[t + 1], 1.0f);
        float d = __fadd_rn(m1, -m2);
        v = __fmul_rn(__fmul_rn(w1[t], w2[t + 1]), __fmul_rn(d, d));
    }
    bv[t] = v; bi[t] = t;
    __syncthreads();
    // max-reduce; on ties keep SMALLEST original index (jnp first-argmax)
    for (int s = 128; s; s >>= 1) {
        if (t < s) {
            float ov = bv[t + s]; int oi = bi[t + s];
            if (ov > bv[t] || (ov == bv[t] && oi < bi[t])) { bv[t] = ov; bi[t] = oi; }
        }
        __syncthreads();
    }
    if (t == 0) g_thresh = c[bi[0]];
}

// ---------------- K4: binarize + tile (smem-staged coalesced stores) -------
__global__ void binarize_kernel(float* __restrict__ out, int npix) {
    __shared__ float4 stage[TB * 3];            // 12 KB
    const float thr = g_thresh;
    const int ngroups = npix >> 2;
    const int nf4     = ngroups * 3;
    const int ntiles  = (ngroups + TB - 1) / TB;
    const float4* __restrict__ gr4 = (const float4*)g_gray;
    float4* __restrict__ o4 = (float4*)out;
    const int t = threadIdx.x;

    for (int tile = blockIdx.x; tile < ntiles; tile += gridDim.x) {
        const int gbase = tile * TB;
        const int g = gbase + t;
        if (g < ngroups) {
            float4 v = gr4[g];
            float b0 = (v.x > thr) ? 1.0f : 0.0f;
            float b1 = (v.y > thr) ? 1.0f : 0.0f;
            float b2 = (v.z > thr) ? 1.0f : 0.0f;
            float b3 = (v.w > thr) ? 1.0f : 0.0f;
            stage[3 * t + 0] = make_float4(b0, b0, b0, b1);
            stage[3 * t + 1] = make_float4(b1, b1, b2, b2);
            stage[3 * t + 2] = make_float4(b2, b3, b3, b3);
        }
        __syncthreads();
        const int fbase = gbase * 3;
        #pragma unroll
        for (int j = 0; j < 3; j++) {
            int idx = t + j * TB;
            if (fbase + idx < nf4) o4[fbase + idx] = stage[idx];
        }
        __syncthreads();
    }
    const int stride = gridDim.x * blockDim.x;
    for (int p = (ngroups << 2) + blockIdx.x * blockDim.x + t; p < npix; p += stride) {
        float b = (g_gray[p] > thr) ? 1.0f : 0.0f;
        out[3 * p + 0] = b;
        out[3 * p + 1] = b;
        out[3 * p + 2] = b;
    }
}

// ---------------- launch ---------------------------------------------------
extern "C" void kernel_launch(void* const* d_in, const int* in_sizes, int n_in,
                              void* d_out, int out_size) {
    const float* in = (const float*)d_in[0];
    float* out = (float*)d_out;
    int npix = in_sizes[0] / 3;

    const int GRID = 148 * 8;

    init_kernel<<<1, 256>>>();
    gray_minmax_kernel<<<GRID, TB>>>(in, npix);
    hist_kernel<<<GRID, TB>>>(npix);
    otsu_kernel<<<1, 256>>>();
    binarize_kernel<<<GRID, TB>>>(out, npix);
}